// round 6
// baseline (speedup 1.0000x reference)
#include <cuda_runtime.h>
#include <cuda_bf16.h>
#include <math.h>

#define B 4
#define C 64
#define L 102400
#define D 192
#define EPSV 1e-12f

#define GK_CHUNK 1024          // L / GK_CHUNK = 100 chunks per batch
#define GK_CHUNKS (L / GK_CHUNK)

// ---------------- device scratch (no allocations allowed) ----------------
__device__ float g_C[B * 128 * 128];   // per-batch Gram of X = [LF; HF]
__device__ float g_T1[B * D * C];      // T1 = Wq @ C_lh
__device__ float g_nq[B * D];
__device__ float g_nk[B * D];
__device__ float g_att[B * D * D];     // softmax rows
__device__ float g_M[B * D * C];       // M = att @ Wv

// ---------------- helpers ----------------
__device__ __forceinline__ unsigned pack_bf16(float x0, float x1) {
    __nv_bfloat16 l = __float2bfloat16(x0);
    __nv_bfloat16 h = __float2bfloat16(x1);
    return ((unsigned)__bfloat16_as_ushort(h) << 16) | (unsigned)__bfloat16_as_ushort(l);
}

__device__ __forceinline__ void mma16816(float* d, const unsigned* a, const unsigned* b) {
    asm volatile(
        "mma.sync.aligned.m16n8k16.row.col.f32.bf16.bf16.f32 "
        "{%0,%1,%2,%3}, {%4,%5,%6,%7}, {%8,%9}, {%0,%1,%2,%3};\n"
        : "+f"(d[0]), "+f"(d[1]), "+f"(d[2]), "+f"(d[3])
        : "r"(a[0]), "r"(a[1]), "r"(a[2]), "r"(a[3]), "r"(b[0]), "r"(b[1]));
}

__device__ __forceinline__ void ldsm_x4(unsigned* r, unsigned addr) {
    asm volatile("ldmatrix.sync.aligned.m8n8.x4.shared.b16 {%0,%1,%2,%3}, [%4];"
                 : "=r"(r[0]), "=r"(r[1]), "=r"(r[2]), "=r"(r[3])
                 : "r"(addr));
}

// ---------------- kernel 0: zero the accumulated Gram ----------------
__global__ void zero_kernel() {
    int i = blockIdx.x * blockDim.x + threadIdx.x;
    if (i < B * 128 * 128) g_C[i] = 0.0f;
}

// ---------------- kernel 1: Gram of X = [LF; HF] via bf16 mma + LDSM ----------------
// grid (GK_CHUNKS, B), 256 threads (8 warps). Warp tile 32(m) x 64(n).
// Global loads register-prefetched one 32-k tile ahead.
__global__ __launch_bounds__(256, 2) void gram_mma_kernel(const float* __restrict__ lf,
                                                          const float* __restrict__ hf) {
    const int b = blockIdx.y;
    const long lbase = (long)blockIdx.x * GK_CHUNK;
    const int tid = threadIdx.x;
    const int wid = tid >> 5;
    const int lane = tid & 31;
    const int g = lane >> 3;    // ldmatrix group 0..3
    const int lr = lane & 7;
    const int gr = lane >> 2;   // mma row group
    const int ct = lane & 3;
    const int m0 = (wid >> 1) * 32;
    const int n0 = (wid & 1) * 64;

    // X tile: 128 rows x 32 k (bf16), row stride 20 words (80B: 16B-aligned, conflict-free)
    __shared__ unsigned Wsh[128 * 20];
    const unsigned sbase = (unsigned)__cvta_generic_to_shared(Wsh);

    // ldmatrix addresses (byte): A frags (m16k16 x4), B frag pairs (two n8k16 per x4)
    unsigned addrA[2], addrB[4];
#pragma unroll
    for (int mt = 0; mt < 2; mt++) {
        int row = m0 + mt * 16 + (g & 1) * 8 + lr;
        addrA[mt] = sbase + (unsigned)(row * 20 + (g >> 1) * 4) * 4u;
    }
#pragma unroll
    for (int p = 0; p < 4; p++) {
        int row = n0 + p * 16 + (g >> 1) * 8 + lr;
        addrB[p] = sbase + (unsigned)(row * 20 + (g & 1) * 4) * 4u;
    }

    // per-thread global-load slots (4 float4 per 128x32 tile)
    const float* srcp[4];
    int dsti[4];
#pragma unroll
    for (int i = 0; i < 4; i++) {
        int idx = i * 256 + tid;
        int row = idx >> 3;
        int fc = idx & 7;
        const float* base = (row < 64)
            ? (lf + ((size_t)(b * 64 + row)) * L)
            : (hf + ((size_t)(b * 64 + row - 64)) * L);
        srcp[i] = base + lbase + fc * 4;
        dsti[i] = row * 20 + fc * 2;
    }

    float acc[2][8][4];
#pragma unroll
    for (int mt = 0; mt < 2; mt++)
#pragma unroll
        for (int nt = 0; nt < 8; nt++)
#pragma unroll
            for (int r = 0; r < 4; r++) acc[mt][nt][r] = 0.0f;

    float4 pre[4];
#pragma unroll
    for (int i = 0; i < 4; i++) pre[i] = *(const float4*)(srcp[i]);

    for (int kt = 0; kt < GK_CHUNK; kt += 32) {
        // commit prefetched tile to shared (bf16)
#pragma unroll
        for (int i = 0; i < 4; i++) {
            Wsh[dsti[i]]     = pack_bf16(pre[i].x, pre[i].y);
            Wsh[dsti[i] + 1] = pack_bf16(pre[i].z, pre[i].w);
        }
        __syncthreads();

        // issue next tile's global loads (latency hidden behind MMAs)
        if (kt + 32 < GK_CHUNK) {
#pragma unroll
            for (int i = 0; i < 4; i++) pre[i] = *(const float4*)(srcp[i] + kt + 32);
        }

#pragma unroll
        for (int k0w = 0; k0w < 16; k0w += 8) {   // two k16 steps
            unsigned afr[2][4], bfr[4][4];
            ldsm_x4(afr[0], addrA[0] + k0w * 4);
            ldsm_x4(afr[1], addrA[1] + k0w * 4);
#pragma unroll
            for (int p = 0; p < 4; p++) ldsm_x4(bfr[p], addrB[p] + k0w * 4);
#pragma unroll
            for (int mt = 0; mt < 2; mt++)
#pragma unroll
                for (int nt = 0; nt < 8; nt++)
                    mma16816(acc[mt][nt], afr[mt], &bfr[nt >> 1][(nt & 1) * 2]);
        }
        __syncthreads();
    }

    float* Cb = g_C + b * 128 * 128;
#pragma unroll
    for (int mt = 0; mt < 2; mt++)
#pragma unroll
        for (int nt = 0; nt < 8; nt++) {
            int row = m0 + mt * 16 + gr;
            int col = n0 + nt * 8 + 2 * ct;
            atomicAdd(&Cb[row * 128 + col],           acc[mt][nt][0]);
            atomicAdd(&Cb[row * 128 + col + 1],       acc[mt][nt][1]);
            atomicAdd(&Cb[(row + 8) * 128 + col],     acc[mt][nt][2]);
            atomicAdd(&Cb[(row + 8) * 128 + col + 1], acc[mt][nt][3]);
        }
}

// ---------------- kernel 2: T1 = Wq @ C_lh ; nq, nk ----------------
__global__ void small_a_kernel(const float* __restrict__ wq,
                               const float* __restrict__ wkv) {
    int row = blockIdx.x;
    int b = blockIdx.y;
    int c = threadIdx.x;   // 0..63
    const float* Cb = g_C + b * 128 * 128;

    __shared__ float wrow[64];
    __shared__ float red[64];

    if (row < D) {
        wrow[c] = wq[row * C + c];
        __syncthreads();
        float t1 = 0.0f, u = 0.0f;
#pragma unroll 8
        for (int cp = 0; cp < 64; cp++) {
            float wv = wrow[cp];
            t1 = fmaf(wv, Cb[cp * 128 + 64 + c], t1);
            u  = fmaf(wv, Cb[cp * 128 + c], u);
        }
        g_T1[((size_t)b * D + row) * C + c] = t1;
        red[c] = u * wrow[c];
        __syncthreads();
        for (int s = 32; s > 0; s >>= 1) {
            if (c < s) red[c] += red[c + s];
            __syncthreads();
        }
        if (c == 0) g_nq[b * D + row] = red[0];
    } else {
        int e = row - D;
        wrow[c] = wkv[e * C + c];
        __syncthreads();
        float u = 0.0f;
#pragma unroll 8
        for (int cp = 0; cp < 64; cp++)
            u = fmaf(wrow[cp], Cb[(64 + cp) * 128 + 64 + c], u);
        red[c] = u * wrow[c];
        __syncthreads();
        for (int s = 32; s > 0; s >>= 1) {
            if (c < s) red[c] += red[c + s];
            __syncthreads();
        }
        if (c == 0) g_nk[b * D + e] = red[0];
    }
}

// ---------------- kernel 3: logits + softmax -> g_att ----------------
// grid (12, B), 256 threads. Block handles 16 d rows; wkv^T staged once per
// block; per-row softmax via warp shuffles (no block-wide reductions).
__global__ void small_b_kernel(const float* __restrict__ wkv) {
    extern __shared__ float sb[];
    float* wshT = sb;                  // 64 * 193
    float* t1s  = sb + 64 * 193;       // 16 * 64
    float* invk = t1s + 16 * 64;       // 192

    const int b = blockIdx.y;
    const int d0 = blockIdx.x * 16;
    const int tid = threadIdx.x;
    const int lane = tid & 31;
    const int w = tid >> 5;

    for (int idx = tid; idx < D * C; idx += 256)
        wshT[(idx & 63) * 193 + (idx >> 6)] = wkv[idx];
    for (int idx = tid; idx < 16 * 64; idx += 256)
        t1s[idx] = g_T1[((size_t)b * D + d0 + (idx >> 6)) * C + (idx & 63)];
    if (tid < D) invk[tid] = 1.0f / fmaxf(sqrtf(g_nk[b * D + tid]), EPSV);
    __syncthreads();

#pragma unroll
    for (int s = 0; s < 2; s++) {
        const int dd = w * 2 + s;
        const int d = d0 + dd;
        const float invq = 1.0f / fmaxf(sqrtf(g_nq[b * D + d]), EPSV);
        const float* t1 = t1s + dd * 64;

        float lg[6];
#pragma unroll
        for (int j = 0; j < 6; j++) {
            int e = j * 32 + lane;
            float gdot = 0.0f;
#pragma unroll 8
            for (int c = 0; c < 64; c++)
                gdot = fmaf(t1[c], wshT[c * 193 + e], gdot);
            lg[j] = gdot * invq * invk[e];
        }
        float mx = lg[0];
#pragma unroll
        for (int j = 1; j < 6; j++) mx = fmaxf(mx, lg[j]);
#pragma unroll
        for (int o = 16; o > 0; o >>= 1)
            mx = fmaxf(mx, __shfl_xor_sync(0xffffffffu, mx, o));
        float sum = 0.0f;
#pragma unroll
        for (int j = 0; j < 6; j++) {
            lg[j] = expf(lg[j] - mx);
            sum += lg[j];
        }
#pragma unroll
        for (int o = 16; o > 0; o >>= 1)
            sum += __shfl_xor_sync(0xffffffffu, sum, o);
        float inv = 1.0f / sum;
#pragma unroll
        for (int j = 0; j < 6; j++)
            g_att[((size_t)b * D + d) * D + j * 32 + lane] = lg[j] * inv;
    }
}

// ---------------- kernel 4: M = att @ Wv ----------------
__global__ void small_c_kernel(const float* __restrict__ wkv) {
    extern __shared__ float sc[];
    float* wv     = sc;                // 192 * 65 (padded)
    float* att_sh = sc + 192 * 65;     // 192 * 192

    int b = blockIdx.x;
    int tid = threadIdx.x;

    for (int idx = tid; idx < D * C; idx += 512)
        wv[(idx >> 6) * 65 + (idx & 63)] = wkv[D * C + idx];
    for (int idx = tid; idx < D * D; idx += 512)
        att_sh[idx] = g_att[(size_t)b * D * D + idx];
    __syncthreads();

    int c = tid & 63;
    int dl = tid >> 6;   // 0..7
    for (int d = dl; d < D; d += 8) {
        float m = 0.0f;
#pragma unroll 8
        for (int k = 0; k < D; k++)
            m = fmaf(att_sh[d * D + k], wv[k * 65 + c], m);
        g_M[((size_t)b * D + d) * C + c] = m;
    }
}

// ---------------- kernel 5: out = M @ HF via split-bf16 mma + LDSM ----------------
// grid (L/64, B), 256 threads (8 warps). C tile 192(d) x 64(l).
// out ~= Mhi*Hhi + Mhi*Hlo + Mlo*Hhi. Warp tile 48(d) x 32(l).
__global__ __launch_bounds__(256, 2) void out_mma_kernel(const float* __restrict__ hf,
                                                         float* __restrict__ out) {
    extern __shared__ unsigned so[];
    unsigned* Mh = so;                    // 192 * 36 words (row stride 36 = 144B)
    unsigned* Ml = Mh + 192 * 36;
    unsigned* Hh = Ml + 192 * 36;         // 64(l) * 36 words ([l][c-pairs])
    unsigned* Hl = Hh + 64 * 36;
    const unsigned MH_B = 0;
    const unsigned ML_B = 192 * 36 * 4;
    const unsigned HH_B = 2 * 192 * 36 * 4;
    const unsigned HL_B = HH_B + 64 * 36 * 4;

    const int b = blockIdx.y;
    const long l0 = (long)blockIdx.x * 64;
    const int tid = threadIdx.x;
    const int wid = tid >> 5;
    const int lane = tid & 31;
    const int g = lane >> 3;
    const int lr = lane & 7;
    const int gr = lane >> 2;
    const int ct = lane & 3;

    // stage M (hi/lo split)
    for (int idx = tid; idx < 192 * 16; idx += 256) {
        int d = idx >> 4;
        int fc = idx & 15;
        float4 v = *(const float4*)(g_M + ((size_t)b * D + d) * C + fc * 4);
        __nv_bfloat16 hx = __float2bfloat16(v.x), hy = __float2bfloat16(v.y);
        __nv_bfloat16 hz = __float2bfloat16(v.z), hw = __float2bfloat16(v.w);
        Mh[d * 36 + fc * 2]     = ((unsigned)__bfloat16_as_ushort(hy) << 16) | __bfloat16_as_ushort(hx);
        Mh[d * 36 + fc * 2 + 1] = ((unsigned)__bfloat16_as_ushort(hw) << 16) | __bfloat16_as_ushort(hz);
        Ml[d * 36 + fc * 2]     = pack_bf16(v.x - __bfloat162float(hx), v.y - __bfloat162float(hy));
        Ml[d * 36 + fc * 2 + 1] = pack_bf16(v.z - __bfloat162float(hz), v.w - __bfloat162float(hw));
    }

    // stage HF tile 64(c) x 64(l), transposed to [l][c-pairs], hi/lo split
    {
        int j = tid >> 4;    // c-pair 0..15
        int lq = tid & 15;   // l/4
#pragma unroll
        for (int p = 0; p < 2; p++) {
            int c = p * 32 + j * 2;
            const float* base0 = hf + ((size_t)b * 64 + c) * L + l0 + lq * 4;
            float4 u0 = *(const float4*)base0;
            float4 u1 = *(const float4*)(base0 + L);
            float a0[4] = {u0.x, u0.y, u0.z, u0.w};
            float a1[4] = {u1.x, u1.y, u1.z, u1.w};
#pragma unroll
            for (int e2 = 0; e2 < 4; e2++) {
                int widx = (lq * 4 + e2) * 36 + p * 16 + j;
                __nv_bfloat16 h0 = __float2bfloat16(a0[e2]);
                __nv_bfloat16 h1 = __float2bfloat16(a1[e2]);
                Hh[widx] = ((unsigned)__bfloat16_as_ushort(h1) << 16) | __bfloat16_as_ushort(h0);
                Hl[widx] = pack_bf16(a0[e2] - __bfloat162float(h0),
                                     a1[e2] - __bfloat162float(h1));
            }
        }
    }
    __syncthreads();

    const int d0w = (wid & 3) * 48;
    const int l0w = (wid >> 2) * 32;
    const unsigned sbase = (unsigned)__cvta_generic_to_shared(so);

    // ldmatrix relative byte offsets
    unsigned aoff[3], boff[2];
#pragma unroll
    for (int mt = 0; mt < 3; mt++) {
        int row = d0w + mt * 16 + (g & 1) * 8 + lr;
        aoff[mt] = (unsigned)(row * 36 + (g >> 1) * 4) * 4u;
    }
#pragma unroll
    for (int p = 0; p < 2; p++) {
        int row = l0w + p * 16 + (g >> 1) * 8 + lr;
        boff[p] = (unsigned)(row * 36 + (g & 1) * 4) * 4u;
    }

    float acc[3][4][4];
#pragma unroll
    for (int mt = 0; mt < 3; mt++)
#pragma unroll
        for (int nt = 0; nt < 4; nt++)
#pragma unroll
            for (int r = 0; r < 4; r++) acc[mt][nt][r] = 0.0f;

#pragma unroll
    for (int pass = 0; pass < 3; pass++) {
        const unsigned abase = sbase + ((pass < 2) ? MH_B : ML_B);
        const unsigned bbase = sbase + ((pass == 1) ? HL_B : HH_B);
#pragma unroll
        for (int c0w = 0; c0w < 32; c0w += 8) {
            unsigned afr[3][4], bfr[2][4];
#pragma unroll
            for (int mt = 0; mt < 3; mt++) ldsm_x4(afr[mt], abase + aoff[mt] + c0w * 4);
#pragma unroll
            for (int p = 0; p < 2; p++)    ldsm_x4(bfr[p], bbase + boff[p] + c0w * 4);
#pragma unroll
            for (int mt = 0; mt < 3; mt++)
#pragma unroll
                for (int nt = 0; nt < 4; nt++)
                    mma16816(acc[mt][nt], afr[mt], &bfr[nt >> 1][(nt & 1) * 2]);
        }
    }

    // epilogue
#pragma unroll
    for (int mt = 0; mt < 3; mt++)
#pragma unroll
        for (int nt = 0; nt < 4; nt++) {
            int d = d0w + mt * 16 + gr;
            int l = l0w + nt * 8 + 2 * ct;
            float2 v0 = make_float2(acc[mt][nt][0], acc[mt][nt][1]);
            float2 v1 = make_float2(acc[mt][nt][2], acc[mt][nt][3]);
            *(float2*)(out + ((size_t)(b * D + d)) * L + l0 + l) = v0;
            *(float2*)(out + ((size_t)(b * D + d + 8)) * L + l0 + l) = v1;
        }
}

// ---------------- launch ----------------
extern "C" void kernel_launch(void* const* d_in, const int* in_sizes, int n_in,
                              void* d_out, int out_size) {
    const float* lf  = (const float*)d_in[0];
    const float* hf  = (const float*)d_in[1];
    const float* wq  = (const float*)d_in[2];
    const float* wkv = (const float*)d_in[3];
    float* out = (float*)d_out;

    static bool attr_done = false;
    const int SMB = (64 * 193 + 16 * 64 + 192) * 4;
    const int SMC = (192 * 65 + 192 * 192) * 4;
    const int SMO = (192 * 36 * 2 + 64 * 36 * 2) * 4;
    if (!attr_done) {
        cudaFuncSetAttribute(small_b_kernel, cudaFuncAttributeMaxDynamicSharedMemorySize, SMB);
        cudaFuncSetAttribute(small_c_kernel, cudaFuncAttributeMaxDynamicSharedMemorySize, SMC);
        cudaFuncSetAttribute(out_mma_kernel, cudaFuncAttributeMaxDynamicSharedMemorySize, SMO);
        attr_done = true;
    }

    zero_kernel<<<(B * 128 * 128 + 255) / 256, 256>>>();
    {
        dim3 grid(GK_CHUNKS, B);
        gram_mma_kernel<<<grid, 256>>>(lf, hf);
    }
    {
        dim3 grid(2 * D, B);
        small_a_kernel<<<grid, 64>>>(wq, wkv);
    }
    {
        dim3 grid(12, B);
        small_b_kernel<<<grid, 256, SMB>>>(wkv);
    }
    small_c_kernel<<<B, 512, SMC>>>(wkv);
    {
        dim3 grid(L / 64, B);
        out_mma_kernel<<<grid, 256, SMO>>>(hf, out);
    }
}

// round 13
// speedup vs baseline: 1.2935x; 1.2935x over previous
#include <cuda_runtime.h>
#include <cuda_fp16.h>
#include <math.h>
#include <stdint.h>

#define B 4
#define C 64
#define L 102400
#define D 192
#define EPSV 1e-12f
#define GK_CHUNK 1024
#define GK_CHUNKS (L / GK_CHUNK)

__device__ float    g_C[B * 128 * 128];
__device__ float    g_T1[B * D * C];
__device__ float    g_nq[B * D];
__device__ float    g_nk[B * D];
__device__ float    g_att[B * D * D];
__device__ unsigned g_Mp[B * D * 32];   // M packed fp16 pairs, 32 words per (b,d) row

__device__ __forceinline__ unsigned pack_f16(float x0, float x1) {
    __half l = __float2half_rn(x0);
    __half h = __float2half_rn(x1);
    return ((unsigned)__half_as_ushort(h) << 16) | (unsigned)__half_as_ushort(l);
}

__device__ __forceinline__ void mma16816_f16(float* d, const unsigned* a, const unsigned* b) {
    asm volatile(
        "mma.sync.aligned.m16n8k16.row.col.f32.f16.f16.f32 "
        "{%0,%1,%2,%3}, {%4,%5,%6,%7}, {%8,%9}, {%0,%1,%2,%3};\n"
        : "+f"(d[0]), "+f"(d[1]), "+f"(d[2]), "+f"(d[3])
        : "r"(a[0]), "r"(a[1]), "r"(a[2]), "r"(a[3]), "r"(b[0]), "r"(b[1]));
}
__device__ __forceinline__ void ldsm_x4(unsigned* r, unsigned addr) {
    asm volatile("ldmatrix.sync.aligned.m8n8.x4.shared.b16 {%0,%1,%2,%3}, [%4];"
                 : "=r"(r[0]), "=r"(r[1]), "=r"(r[2]), "=r"(r[3])
                 : "r"(addr));
}

// ---------------- kernel 0: zero g_C ----------------
__global__ void zero_kernel() {
    int i = blockIdx.x * blockDim.x + threadIdx.x;
    if (i < B * 128 * 128) g_C[i] = 0.0f;
}

// ---------------- kernel 1: Gram of X=[LF;HF] via fp16 mma + LDSM ----------------
// grid (GK_CHUNKS, B), 256 threads (8 warps). Warp tile 32(m) x 64(n).
__global__ __launch_bounds__(256, 2) void gram_mma_kernel(const float* __restrict__ lf,
                                                          const float* __restrict__ hf) {
    const int b = blockIdx.y;
    const long lbase = (long)blockIdx.x * GK_CHUNK;
    const int tid = threadIdx.x;
    const int wid = tid >> 5, lane = tid & 31;
    const int g = lane >> 3, lr = lane & 7, gr = lane >> 2, ct = lane & 3;
    const int m0 = (wid >> 1) * 32, n0 = (wid & 1) * 64;

    __shared__ unsigned Wsh[128 * 20];
    const unsigned sbase = (unsigned)__cvta_generic_to_shared(Wsh);

    unsigned addrA[2], addrB[4];
#pragma unroll
    for (int mt = 0; mt < 2; mt++) {
        int row = m0 + mt * 16 + (g & 1) * 8 + lr;
        addrA[mt] = sbase + (unsigned)(row * 20 + (g >> 1) * 4) * 4u;
    }
#pragma unroll
    for (int p = 0; p < 4; p++) {
        int row = n0 + p * 16 + (g >> 1) * 8 + lr;
        addrB[p] = sbase + (unsigned)(row * 20 + (g & 1) * 4) * 4u;
    }

    const float* srcp[4];
    int dsti[4];
#pragma unroll
    for (int i = 0; i < 4; i++) {
        int idx = i * 256 + tid;
        int row = idx >> 3, fc = idx & 7;
        const float* base = (row < 64) ? (lf + (size_t)(b * 64 + row) * L)
                                       : (hf + (size_t)(b * 64 + row - 64) * L);
        srcp[i] = base + lbase + fc * 4;
        dsti[i] = row * 20 + fc * 2;
    }

    float acc[2][8][4];
#pragma unroll
    for (int mt = 0; mt < 2; mt++)
#pragma unroll
        for (int nt = 0; nt < 8; nt++)
#pragma unroll
            for (int r = 0; r < 4; r++) acc[mt][nt][r] = 0.0f;

    float4 pre[4];
#pragma unroll
    for (int i = 0; i < 4; i++) pre[i] = *(const float4*)(srcp[i]);

    for (int kt = 0; kt < GK_CHUNK; kt += 32) {
#pragma unroll
        for (int i = 0; i < 4; i++) {
            Wsh[dsti[i]]     = pack_f16(pre[i].x, pre[i].y);
            Wsh[dsti[i] + 1] = pack_f16(pre[i].z, pre[i].w);
        }
        __syncthreads();
        if (kt + 32 < GK_CHUNK) {
#pragma unroll
            for (int i = 0; i < 4; i++) pre[i] = *(const float4*)(srcp[i] + kt + 32);
        }
#pragma unroll
        for (int k0w = 0; k0w < 16; k0w += 8) {
            unsigned afr[2][4], bfr[4][4];
            ldsm_x4(afr[0], addrA[0] + k0w * 4);
            ldsm_x4(afr[1], addrA[1] + k0w * 4);
#pragma unroll
            for (int p = 0; p < 4; p++) ldsm_x4(bfr[p], addrB[p] + k0w * 4);
#pragma unroll
            for (int mt = 0; mt < 2; mt++)
#pragma unroll
                for (int nt = 0; nt < 8; nt++)
                    mma16816_f16(acc[mt][nt], afr[mt], &bfr[nt >> 1][(nt & 1) * 2]);
        }
        __syncthreads();
    }

    float* Cb = g_C + b * 128 * 128;
#pragma unroll
    for (int mt = 0; mt < 2; mt++)
#pragma unroll
        for (int nt = 0; nt < 8; nt++) {
            int row = m0 + mt * 16 + gr, col = n0 + nt * 8 + 2 * ct;
            atomicAdd(&Cb[row * 128 + col],           acc[mt][nt][0]);
            atomicAdd(&Cb[row * 128 + col + 1],       acc[mt][nt][1]);
            atomicAdd(&Cb[(row + 8) * 128 + col],     acc[mt][nt][2]);
            atomicAdd(&Cb[(row + 8) * 128 + col + 1], acc[mt][nt][3]);
        }
}

// ---------------- kernel 2: T1 = Wq @ C_lh ; nq, nk ----------------
__global__ void small_a_kernel(const float* __restrict__ wq,
                               const float* __restrict__ wkv) {
    int row = blockIdx.x, b = blockIdx.y, c = threadIdx.x;
    const float* Cb = g_C + b * 128 * 128;
    __shared__ float wrow[64];
    __shared__ float red[64];
    if (row < D) {
        wrow[c] = wq[row * C + c];
        __syncthreads();
        float t1 = 0.0f, u = 0.0f;
#pragma unroll 8
        for (int cp = 0; cp < 64; cp++) {
            float wv = wrow[cp];
            t1 = fmaf(wv, Cb[cp * 128 + 64 + c], t1);
            u  = fmaf(wv, Cb[cp * 128 + c], u);
        }
        g_T1[((size_t)b * D + row) * C + c] = t1;
        red[c] = u * wrow[c];
        __syncthreads();
        for (int s = 32; s > 0; s >>= 1) { if (c < s) red[c] += red[c + s]; __syncthreads(); }
        if (c == 0) g_nq[b * D + row] = red[0];
    } else {
        int e = row - D;
        wrow[c] = wkv[e * C + c];
        __syncthreads();
        float u = 0.0f;
#pragma unroll 8
        for (int cp = 0; cp < 64; cp++)
            u = fmaf(wrow[cp], Cb[(64 + cp) * 128 + 64 + c], u);
        red[c] = u * wrow[c];
        __syncthreads();
        for (int s = 32; s > 0; s >>= 1) { if (c < s) red[c] += red[c + s]; __syncthreads(); }
        if (c == 0) g_nk[b * D + e] = red[0];
    }
}

// ---------------- kernel 3: logits + softmax -> g_att ----------------
__global__ void small_b_kernel(const float* __restrict__ wkv) {
    extern __shared__ float sb[];
    float* wshT = sb;                  // 64*193
    float* t1s  = sb + 64 * 193;       // 16*64
    float* invk = t1s + 16 * 64;       // 192
    const int b = blockIdx.y, d0 = blockIdx.x * 16;
    const int tid = threadIdx.x, lane = tid & 31, w = tid >> 5;

    for (int idx = tid; idx < D * C; idx += 256)
        wshT[(idx & 63) * 193 + (idx >> 6)] = wkv[idx];
    for (int idx = tid; idx < 16 * 64; idx += 256)
        t1s[idx] = g_T1[((size_t)b * D + d0 + (idx >> 6)) * C + (idx & 63)];
    if (tid < D) invk[tid] = 1.0f / fmaxf(sqrtf(g_nk[b * D + tid]), EPSV);
    __syncthreads();

#pragma unroll
    for (int s = 0; s < 2; s++) {
        const int dd = w * 2 + s, d = d0 + dd;
        const float invq = 1.0f / fmaxf(sqrtf(g_nq[b * D + d]), EPSV);
        const float* t1 = t1s + dd * 64;
        float lg[6];
#pragma unroll
        for (int j = 0; j < 6; j++) {
            int e = j * 32 + lane;
            float gd = 0.0f;
#pragma unroll 8
            for (int c = 0; c < 64; c++) gd = fmaf(t1[c], wshT[c * 193 + e], gd);
            lg[j] = gd * invq * invk[e];
        }
        float mx = lg[0];
#pragma unroll
        for (int j = 1; j < 6; j++) mx = fmaxf(mx, lg[j]);
#pragma unroll
        for (int o = 16; o > 0; o >>= 1) mx = fmaxf(mx, __shfl_xor_sync(~0u, mx, o));
        float sum = 0.0f;
#pragma unroll
        for (int j = 0; j < 6; j++) { lg[j] = expf(lg[j] - mx); sum += lg[j]; }
#pragma unroll
        for (int o = 16; o > 0; o >>= 1) sum += __shfl_xor_sync(~0u, sum, o);
        float inv = 1.0f / sum;
#pragma unroll
        for (int j = 0; j < 6; j++)
            g_att[((size_t)b * D + d) * D + j * 32 + lane] = lg[j] * inv;
    }
}

// ---------------- kernel 4: M = att @ Wv, packed fp16 ----------------
__global__ void small_c_kernel(const float* __restrict__ wkv) {
    extern __shared__ float sc[];
    float* wv = sc;                    // 192*65
    float* att_sh = sc + 192 * 65;     // 192*192
    int b = blockIdx.x, tid = threadIdx.x;
    for (int idx = tid; idx < D * C; idx += 512)
        wv[(idx >> 6) * 65 + (idx & 63)] = wkv[D * C + idx];
    for (int idx = tid; idx < D * D; idx += 512)
        att_sh[idx] = g_att[(size_t)b * D * D + idx];
    __syncthreads();
    int c2 = tid & 31, dl = tid >> 5;   // c pair, d lane (0..15)
    for (int d = dl; d < D; d += 16) {
        float m0 = 0.0f, m1 = 0.0f;
#pragma unroll 8
        for (int k = 0; k < D; k++) {
            float a = att_sh[d * D + k];
            m0 = fmaf(a, wv[k * 65 + 2 * c2], m0);
            m1 = fmaf(a, wv[k * 65 + 2 * c2 + 1], m1);
        }
        g_Mp[(size_t)(b * D + d) * 32 + c2] = pack_f16(m0, m1);
    }
}

// ---------------- kernel 5: out = M @ HF, single fp16 pass ----------------
// grid (L/256, B), 256 thr (8 warps). Block: 192(d) x 256(l) as 4 sub-tiles
// of 64 l. M staged once (fp16 pre-packed), H staged per sub-tile with reg
// prefetch. Warp tile 48(d) x 32(l).
__global__ __launch_bounds__(256, 2) void out_f16_kernel(const float* __restrict__ hf,
                                                         float* __restrict__ out) {
    __shared__ unsigned Msh[192 * 36];   // row stride 36 words
    __shared__ unsigned Hsh[64 * 36];    // [l][c-pair], stride 36

    const int b = blockIdx.y;
    const long l0 = (long)blockIdx.x * 256;
    const int tid = threadIdx.x;
    const int wid = tid >> 5, lane = tid & 31;
    const int g = lane >> 3, lr = lane & 7, gr = lane >> 2, ct = lane & 3;

    // stage M: copy packed rows (32 words) into stride-36 smem
    for (int idx = tid; idx < 192 * 8; idx += 256) {
        int d = idx >> 3, q = idx & 3;     // note: 8 uint4 per row
        int qq = idx & 7;
        (void)q;
        uint4 v = *(const uint4*)(g_Mp + (size_t)(b * D + d) * 32 + qq * 4);
        *(uint4*)(Msh + d * 36 + qq * 4) = v;
    }

    // H staging slots: thread covers (c pair group j, l quad lq) x 2 halves
    const int j = tid >> 4;    // 0..15 c-pair
    const int lq = tid & 15;   // l/4
    const float* hbase0 = hf + ((size_t)(b * 64 + 2 * j)) * L + l0 + lq * 4;
    const float* hbase1 = hf + ((size_t)(b * 64 + 32 + 2 * j)) * L + l0 + lq * 4;

    const unsigned sbM = (unsigned)__cvta_generic_to_shared(Msh);
    const unsigned sbH = (unsigned)__cvta_generic_to_shared(Hsh);
    const int d0w = (wid & 3) * 48;
    const int l0w = (wid >> 2) * 32;

    unsigned aoff[3], boff[2];
#pragma unroll
    for (int mt = 0; mt < 3; mt++) {
        int row = d0w + mt * 16 + (g & 1) * 8 + lr;
        aoff[mt] = sbM + (unsigned)(row * 36 + (g >> 1) * 4) * 4u;
    }
#pragma unroll
    for (int p = 0; p < 2; p++) {
        int row = l0w + p * 16 + (g >> 1) * 8 + lr;
        boff[p] = sbH + (unsigned)(row * 36 + (g & 1) * 4) * 4u;
    }

    float4 pre[4];   // [half p][u0/u1]
    {
        pre[0] = *(const float4*)hbase0;
        pre[1] = *(const float4*)(hbase0 + L);
        pre[2] = *(const float4*)hbase1;
        pre[3] = *(const float4*)(hbase1 + L);
    }

    for (int it = 0; it < 4; it++) {
        __syncthreads();   // prior sub-tile's mma reads done
        // commit prefetched H sub-tile (fp16, transposed [l][c-pair])
#pragma unroll
        for (int p = 0; p < 2; p++) {
            float4 u0 = pre[2 * p], u1 = pre[2 * p + 1];
            float a0[4] = {u0.x, u0.y, u0.z, u0.w};
            float a1[4] = {u1.x, u1.y, u1.z, u1.w};
#pragma unroll
            for (int e2 = 0; e2 < 4; e2++)
                Hsh[(lq * 4 + e2) * 36 + p * 16 + j] = pack_f16(a0[e2], a1[e2]);
        }
        __syncthreads();
        // prefetch next sub-tile
        if (it < 3) {
            int o = (it + 1) * 64;
            pre[0] = *(const float4*)(hbase0 + o);
            pre[1] = *(const float4*)(hbase0 + o + L);
            pre[2] = *(const float4*)(hbase1 + o);
            pre[3] = *(const float4*)(hbase1 + o + L);
        }

        float acc[3][4][4];
#pragma unroll
        for (int mt = 0; mt < 3; mt++)
#pragma unroll
            for (int nt = 0; nt < 4; nt++)
#pragma unroll
                for (int r = 0; r < 4; r++) acc[mt][nt][r] = 0.0f;

#pragma unroll
        for (int c0w = 0; c0w < 32; c0w += 8) {
            unsigned afr[3][4], bfr[2][4];
#pragma unroll
            for (int mt = 0; mt < 3; mt++) ldsm_x4(afr[mt], aoff[mt] + c0w * 4);
#pragma unroll
            for (int p = 0; p < 2; p++)    ldsm_x4(bfr[p], boff[p] + c0w * 4);
#pragma unroll
            for (int mt = 0; mt < 3; mt++)
#pragma unroll
                for (int nt = 0; nt < 4; nt++)
                    mma16816_f16(acc[mt][nt], afr[mt], &bfr[nt >> 1][(nt & 1) * 2]);
        }

        const long lbase = l0 + it * 64;
#pragma unroll
        for (int mt = 0; mt < 3; mt++)
#pragma unroll
            for (int nt = 0; nt < 4; nt++) {
                int d = d0w + mt * 16 + gr;
                int l = l0w + nt * 8 + 2 * ct;
                float2 v0 = make_float2(acc[mt][nt][0], acc[mt][nt][1]);
                float2 v1 = make_float2(acc[mt][nt][2], acc[mt][nt][3]);
                *(float2*)(out + ((size_t)(b * D + d)) * L + lbase + l) = v0;
                *(float2*)(out + ((size_t)(b * D + d + 8)) * L + lbase + l) = v1;
            }
    }
}

// ---------------- launch ----------------
extern "C" void kernel_launch(void* const* d_in, const int* in_sizes, int n_in,
                              void* d_out, int out_size) {
    const float* lf  = (const float*)d_in[0];
    const float* hf  = (const float*)d_in[1];
    const float* wq  = (const float*)d_in[2];
    const float* wkv = (const float*)d_in[3];
    float* out = (float*)d_out;

    static bool attr_done = false;
    const int SMB = (64 * 193 + 16 * 64 + 192) * 4;
    const int SMC = (192 * 65 + 192 * 192) * 4;
    if (!attr_done) {
        cudaFuncSetAttribute(small_b_kernel, cudaFuncAttributeMaxDynamicSharedMemorySize, SMB);
        cudaFuncSetAttribute(small_c_kernel, cudaFuncAttributeMaxDynamicSharedMemorySize, SMC);
        attr_done = true;
    }

    zero_kernel<<<(B * 128 * 128 + 255) / 256, 256>>>();
    { dim3 g(GK_CHUNKS, B); gram_mma_kernel<<<g, 256>>>(lf, hf); }
    { dim3 g(2 * D, B); small_a_kernel<<<g, 64>>>(wq, wkv); }
    { dim3 g(12, B); small_b_kernel<<<g, 256, SMB>>>(wkv); }
    small_c_kernel<<<B, 512, SMC>>>(wkv);
    { dim3 g(L / 256, B); out_f16_kernel<<<g, 256>>>(hf, out); }
}

// round 14
// speedup vs baseline: 1.8224x; 1.4089x over previous
#include <cuda_runtime.h>
#include <cuda_fp16.h>
#include <math.h>
#include <stdint.h>

#define B 4
#define C 64
#define L 102400
#define D 192
#define EPSV 1e-12f
#define GK_CHUNK 1600          // 64 chunks/batch -> 256 blocks = 1 full wave @ occ 2
#define GK_CHUNKS (L / GK_CHUNK)

__device__ float    g_C[B * 128 * 128];
__device__ float    g_T1[B * D * C];
__device__ float    g_nq[B * D];
__device__ float    g_nk[B * D];
__device__ unsigned g_Mp[B * D * 32];   // M packed fp16 pairs, 32 words per (b,d) row

__device__ __forceinline__ unsigned pack_f16(float x0, float x1) {
    __half l = __float2half_rn(x0);
    __half h = __float2half_rn(x1);
    return ((unsigned)__half_as_ushort(h) << 16) | (unsigned)__half_as_ushort(l);
}

__device__ __forceinline__ void mma16816_f16(float* d, const unsigned* a, const unsigned* b) {
    asm volatile(
        "mma.sync.aligned.m16n8k16.row.col.f32.f16.f16.f32 "
        "{%0,%1,%2,%3}, {%4,%5,%6,%7}, {%8,%9}, {%0,%1,%2,%3};\n"
        : "+f"(d[0]), "+f"(d[1]), "+f"(d[2]), "+f"(d[3])
        : "r"(a[0]), "r"(a[1]), "r"(a[2]), "r"(a[3]), "r"(b[0]), "r"(b[1]));
}
__device__ __forceinline__ void ldsm_x4(unsigned* r, unsigned addr) {
    asm volatile("ldmatrix.sync.aligned.m8n8.x4.shared.b16 {%0,%1,%2,%3}, [%4];"
                 : "=r"(r[0]), "=r"(r[1]), "=r"(r[2]), "=r"(r[3])
                 : "r"(addr));
}

// ---------------- kernel 0: zero g_C ----------------
__global__ void zero_kernel() {
    int i = blockIdx.x * blockDim.x + threadIdx.x;
    if (i < B * 128 * 128) g_C[i] = 0.0f;
}

// ---------------- kernel 1: Gram of X=[LF;HF] via fp16 mma + LDSM ----------------
// grid (GK_CHUNKS, B) = 256 blocks total, 256 threads (8 warps).
// Warp tile 32(m) x 64(n). Global loads register-prefetched one 32-k tile ahead.
__global__ __launch_bounds__(256, 2) void gram_mma_kernel(const float* __restrict__ lf,
                                                          const float* __restrict__ hf) {
    const int b = blockIdx.y;
    const long lbase = (long)blockIdx.x * GK_CHUNK;
    const int tid = threadIdx.x;
    const int wid = tid >> 5, lane = tid & 31;
    const int g = lane >> 3, lr = lane & 7, gr = lane >> 2, ct = lane & 3;
    const int m0 = (wid >> 1) * 32, n0 = (wid & 1) * 64;

    __shared__ unsigned Wsh[128 * 20];
    const unsigned sbase = (unsigned)__cvta_generic_to_shared(Wsh);

    unsigned addrA[2], addrB[4];
#pragma unroll
    for (int mt = 0; mt < 2; mt++) {
        int row = m0 + mt * 16 + (g & 1) * 8 + lr;
        addrA[mt] = sbase + (unsigned)(row * 20 + (g >> 1) * 4) * 4u;
    }
#pragma unroll
    for (int p = 0; p < 4; p++) {
        int row = n0 + p * 16 + (g >> 1) * 8 + lr;
        addrB[p] = sbase + (unsigned)(row * 20 + (g & 1) * 4) * 4u;
    }

    const float* srcp[4];
    int dsti[4];
#pragma unroll
    for (int i = 0; i < 4; i++) {
        int idx = i * 256 + tid;
        int row = idx >> 3, fc = idx & 7;
        const float* base = (row < 64) ? (lf + (size_t)(b * 64 + row) * L)
                                       : (hf + (size_t)(b * 64 + row - 64) * L);
        srcp[i] = base + lbase + fc * 4;
        dsti[i] = row * 20 + fc * 2;
    }

    float acc[2][8][4];
#pragma unroll
    for (int mt = 0; mt < 2; mt++)
#pragma unroll
        for (int nt = 0; nt < 8; nt++)
#pragma unroll
            for (int r = 0; r < 4; r++) acc[mt][nt][r] = 0.0f;

    float4 pre[4];
#pragma unroll
    for (int i = 0; i < 4; i++) pre[i] = *(const float4*)(srcp[i]);

    for (int kt = 0; kt < GK_CHUNK; kt += 32) {
#pragma unroll
        for (int i = 0; i < 4; i++) {
            Wsh[dsti[i]]     = pack_f16(pre[i].x, pre[i].y);
            Wsh[dsti[i] + 1] = pack_f16(pre[i].z, pre[i].w);
        }
        __syncthreads();
        if (kt + 32 < GK_CHUNK) {
#pragma unroll
            for (int i = 0; i < 4; i++) pre[i] = *(const float4*)(srcp[i] + kt + 32);
        }
#pragma unroll
        for (int k0w = 0; k0w < 16; k0w += 8) {
            unsigned afr[2][4], bfr[4][4];
            ldsm_x4(afr[0], addrA[0] + k0w * 4);
            ldsm_x4(afr[1], addrA[1] + k0w * 4);
#pragma unroll
            for (int p = 0; p < 4; p++) ldsm_x4(bfr[p], addrB[p] + k0w * 4);
#pragma unroll
            for (int mt = 0; mt < 2; mt++)
#pragma unroll
                for (int nt = 0; nt < 8; nt++)
                    mma16816_f16(acc[mt][nt], afr[mt], &bfr[nt >> 1][(nt & 1) * 2]);
        }
        __syncthreads();
    }

    float* Cb = g_C + b * 128 * 128;
#pragma unroll
    for (int mt = 0; mt < 2; mt++)
#pragma unroll
        for (int nt = 0; nt < 8; nt++) {
            int row = m0 + mt * 16 + gr, col = n0 + nt * 8 + 2 * ct;
            atomicAdd(&Cb[row * 128 + col],           acc[mt][nt][0]);
            atomicAdd(&Cb[row * 128 + col + 1],       acc[mt][nt][1]);
            atomicAdd(&Cb[(row + 8) * 128 + col],     acc[mt][nt][2]);
            atomicAdd(&Cb[(row + 8) * 128 + col + 1], acc[mt][nt][3]);
        }
}

// ---------------- kernel 2: T1 = Wq @ C_lh ; nq, nk ----------------
__global__ void small_a_kernel(const float* __restrict__ wq,
                               const float* __restrict__ wkv) {
    int row = blockIdx.x, b = blockIdx.y, c = threadIdx.x;
    const float* Cb = g_C + b * 128 * 128;
    __shared__ float wrow[64];
    __shared__ float red[64];
    if (row < D) {
        wrow[c] = wq[row * C + c];
        __syncthreads();
        float t1 = 0.0f, u = 0.0f;
#pragma unroll 8
        for (int cp = 0; cp < 64; cp++) {
            float wv = wrow[cp];
            t1 = fmaf(wv, Cb[cp * 128 + 64 + c], t1);
            u  = fmaf(wv, Cb[cp * 128 + c], u);
        }
        g_T1[((size_t)b * D + row) * C + c] = t1;
        red[c] = u * wrow[c];
        __syncthreads();
        for (int s = 32; s > 0; s >>= 1) { if (c < s) red[c] += red[c + s]; __syncthreads(); }
        if (c == 0) g_nq[b * D + row] = red[0];
    } else {
        int e = row - D;
        wrow[c] = wkv[e * C + c];
        __syncthreads();
        float u = 0.0f;
#pragma unroll 8
        for (int cp = 0; cp < 64; cp++)
            u = fmaf(wrow[cp], Cb[(64 + cp) * 128 + 64 + c], u);
        red[c] = u * wrow[c];
        __syncthreads();
        for (int s = 32; s > 0; s >>= 1) { if (c < s) red[c] += red[c + s]; __syncthreads(); }
        if (c == 0) g_nk[b * D + e] = red[0];
    }
}

// ---------------- kernel 3: fused logits + softmax + M = att @ Wv ----------------
// grid (12, B), 256 threads. 16 d-rows per block. att stays in smem; M rows
// written directly as packed fp16 (no g_att round trip, no separate kernel).
__global__ void small_bc_kernel(const float* __restrict__ wkv) {
    extern __shared__ float sb[];
    float* wshT   = sb;                         // 64*193   (Wk^T for logits)
    float* wv     = wshT + 64 * 193;            // 192*65   (Wv [k][c])
    float* t1s    = wv + 192 * 65;              // 16*64
    float* invk   = t1s + 16 * 64;              // 192
    float* att_sh = invk + 192;                 // 16*192

    const int b = blockIdx.y, d0 = blockIdx.x * 16;
    const int tid = threadIdx.x, lane = tid & 31, w = tid >> 5;

    for (int idx = tid; idx < D * C; idx += 256)
        wshT[(idx & 63) * 193 + (idx >> 6)] = wkv[idx];
    for (int idx = tid; idx < D * C; idx += 256)
        wv[(idx >> 6) * 65 + (idx & 63)] = wkv[D * C + idx];
    for (int idx = tid; idx < 16 * 64; idx += 256)
        t1s[idx] = g_T1[((size_t)b * D + d0 + (idx >> 6)) * C + (idx & 63)];
    if (tid < D) invk[tid] = 1.0f / fmaxf(sqrtf(g_nk[b * D + tid]), EPSV);
    __syncthreads();

    // phase 2: logits + softmax, one warp per 2 d-rows
#pragma unroll
    for (int s = 0; s < 2; s++) {
        const int dd = w * 2 + s, d = d0 + dd;
        const float invq = 1.0f / fmaxf(sqrtf(g_nq[b * D + d]), EPSV);
        const float* t1 = t1s + dd * 64;
        float lg[6];
#pragma unroll
        for (int j = 0; j < 6; j++) {
            int e = j * 32 + lane;
            float gd = 0.0f;
#pragma unroll 8
            for (int c = 0; c < 64; c++) gd = fmaf(t1[c], wshT[c * 193 + e], gd);
            lg[j] = gd * invq * invk[e];
        }
        float mx = lg[0];
#pragma unroll
        for (int j = 1; j < 6; j++) mx = fmaxf(mx, lg[j]);
#pragma unroll
        for (int o = 16; o > 0; o >>= 1) mx = fmaxf(mx, __shfl_xor_sync(~0u, mx, o));
        float sum = 0.0f;
#pragma unroll
        for (int j = 0; j < 6; j++) { lg[j] = expf(lg[j] - mx); sum += lg[j]; }
#pragma unroll
        for (int o = 16; o > 0; o >>= 1) sum += __shfl_xor_sync(~0u, sum, o);
        float inv = 1.0f / sum;
#pragma unroll
        for (int j = 0; j < 6; j++)
            att_sh[dd * 192 + j * 32 + lane] = lg[j] * inv;
    }
    __syncthreads();

    // phase 3: M rows (packed fp16). thread (c2, dl) does rows dl, dl+8.
    const int c2 = tid & 31, dl = tid >> 5;
#pragma unroll
    for (int h = 0; h < 2; h++) {
        int dd = dl + h * 8;
        const float* att = att_sh + dd * 192;
        float m0 = 0.0f, m1 = 0.0f;
#pragma unroll 8
        for (int k = 0; k < D; k++) {
            float a = att[k];
            m0 = fmaf(a, wv[k * 65 + 2 * c2], m0);
            m1 = fmaf(a, wv[k * 65 + 2 * c2 + 1], m1);
        }
        g_Mp[(size_t)(b * D + d0 + dd) * 32 + c2] = pack_f16(m0, m1);
    }
}

// ---------------- kernel 4: out = M @ HF, single fp16 pass ----------------
// grid (L/256, B), 256 thr (8 warps). Block: 192(d) x 256(l) as 4 sub-tiles.
__global__ __launch_bounds__(256, 2) void out_f16_kernel(const float* __restrict__ hf,
                                                         float* __restrict__ out) {
    __shared__ unsigned Msh[192 * 36];
    __shared__ unsigned Hsh[64 * 36];

    const int b = blockIdx.y;
    const long l0 = (long)blockIdx.x * 256;
    const int tid = threadIdx.x;
    const int wid = tid >> 5, lane = tid & 31;
    const int g = lane >> 3, lr = lane & 7, gr = lane >> 2, ct = lane & 3;

    for (int idx = tid; idx < 192 * 8; idx += 256) {
        int d = idx >> 3, qq = idx & 7;
        uint4 v = *(const uint4*)(g_Mp + (size_t)(b * D + d) * 32 + qq * 4);
        *(uint4*)(Msh + d * 36 + qq * 4) = v;
    }

    const int j = tid >> 4;    // c-pair 0..15
    const int lq = tid & 15;   // l/4
    const float* hbase0 = hf + ((size_t)(b * 64 + 2 * j)) * L + l0 + lq * 4;
    const float* hbase1 = hf + ((size_t)(b * 64 + 32 + 2 * j)) * L + l0 + lq * 4;

    const unsigned sbM = (unsigned)__cvta_generic_to_shared(Msh);
    const unsigned sbH = (unsigned)__cvta_generic_to_shared(Hsh);
    const int d0w = (wid & 3) * 48;
    const int l0w = (wid >> 2) * 32;

    unsigned aoff[3], boff[2];
#pragma unroll
    for (int mt = 0; mt < 3; mt++) {
        int row = d0w + mt * 16 + (g & 1) * 8 + lr;
        aoff[mt] = sbM + (unsigned)(row * 36 + (g >> 1) * 4) * 4u;
    }
#pragma unroll
    for (int p = 0; p < 2; p++) {
        int row = l0w + p * 16 + (g >> 1) * 8 + lr;
        boff[p] = sbH + (unsigned)(row * 36 + (g & 1) * 4) * 4u;
    }

    float4 pre[4];
    pre[0] = *(const float4*)hbase0;
    pre[1] = *(const float4*)(hbase0 + L);
    pre[2] = *(const float4*)hbase1;
    pre[3] = *(const float4*)(hbase1 + L);

    for (int it = 0; it < 4; it++) {
        __syncthreads();
#pragma unroll
        for (int p = 0; p < 2; p++) {
            float4 u0 = pre[2 * p], u1 = pre[2 * p + 1];
            float a0[4] = {u0.x, u0.y, u0.z, u0.w};
            float a1[4] = {u1.x, u1.y, u1.z, u1.w};
#pragma unroll
            for (int e2 = 0; e2 < 4; e2++)
                Hsh[(lq * 4 + e2) * 36 + p * 16 + j] = pack_f16(a0[e2], a1[e2]);
        }
        __syncthreads();
        if (it < 3) {
            int o = (it + 1) * 64;
            pre[0] = *(const float4*)(hbase0 + o);
            pre[1] = *(const float4*)(hbase0 + o + L);
            pre[2] = *(const float4*)(hbase1 + o);
            pre[3] = *(const float4*)(hbase1 + o + L);
        }

        float acc[3][4][4];
#pragma unroll
        for (int mt = 0; mt < 3; mt++)
#pragma unroll
            for (int nt = 0; nt < 4; nt++)
#pragma unroll
                for (int r = 0; r < 4; r++) acc[mt][nt][r] = 0.0f;

#pragma unroll
        for (int c0w = 0; c0w < 32; c0w += 8) {
            unsigned afr[3][4], bfr[2][4];
#pragma unroll
            for (int mt = 0; mt < 3; mt++) ldsm_x4(afr[mt], aoff[mt] + c0w * 4);
#pragma unroll
            for (int p = 0; p < 2; p++)    ldsm_x4(bfr[p], boff[p] + c0w * 4);
#pragma unroll
            for (int mt = 0; mt < 3; mt++)
#pragma unroll
                for (int nt = 0; nt < 4; nt++)
                    mma16816_f16(acc[mt][nt], afr[mt], &bfr[nt >> 1][(nt & 1) * 2]);
        }

        const long lbase = l0 + it * 64;
#pragma unroll
        for (int mt = 0; mt < 3; mt++)
#pragma unroll
            for (int nt = 0; nt < 4; nt++) {
                int d = d0w + mt * 16 + gr;
                int l = l0w + nt * 8 + 2 * ct;
                float2 v0 = make_float2(acc[mt][nt][0], acc[mt][nt][1]);
                float2 v1 = make_float2(acc[mt][nt][2], acc[mt][nt][3]);
                *(float2*)(out + ((size_t)(b * D + d)) * L + lbase + l) = v0;
                *(float2*)(out + ((size_t)(b * D + d + 8)) * L + lbase + l) = v1;
            }
    }
}

// ---------------- launch ----------------
extern "C" void kernel_launch(void* const* d_in, const int* in_sizes, int n_in,
                              void* d_out, int out_size) {
    const float* lf  = (const float*)d_in[0];
    const float* hf  = (const float*)d_in[1];
    const float* wq  = (const float*)d_in[2];
    const float* wkv = (const float*)d_in[3];
    float* out = (float*)d_out;

    static bool attr_done = false;
    const int SMBC = (64 * 193 + 192 * 65 + 16 * 64 + 192 + 16 * 192) * 4;
    if (!attr_done) {
        cudaFuncSetAttribute(small_bc_kernel, cudaFuncAttributeMaxDynamicSharedMemorySize, SMBC);
        attr_done = true;
    }

    zero_kernel<<<(B * 128 * 128 + 255) / 256, 256>>>();
    { dim3 g(GK_CHUNKS, B); gram_mma_kernel<<<g, 256>>>(lf, hf); }
    { dim3 g(2 * D, B); small_a_kernel<<<g, 64>>>(wq, wkv); }
    { dim3 g(12, B); small_bc_kernel<<<g, 256, SMBC>>>(wkv); }
    { dim3 g(L / 256, B); out_f16_kernel<<<g, 256>>>(hf, out); }
}